// round 7
// baseline (speedup 1.0000x reference)
#include <cuda_runtime.h>
#include <cuda_bf16.h>
#include <cstdint>
#include <math.h>

#define NTOK   49
#define HEADS  6
#define DIM    192
#define DH     32
#define QSCALE 0.1767766952966369f

/* ================= device scratch (static: allocation-free) ================= */
__device__ float          g_qkv [200704u * 576u];
__device__ float          g_attn[200704u * 192u];
__device__ __nv_bfloat16  g_wqh[576 * 192], g_wql[576 * 192];
__device__ __nv_bfloat16  g_wph[192 * 192], g_wpl[192 * 192];
__device__ float          g_bias[HEADS * NTOK * NTOK];

__device__ __forceinline__ uint32_t pack_bf2(float a, float b) {
    __nv_bfloat16 ha = __float2bfloat16(a), hb = __float2bfloat16(b);
    return (uint32_t)__bfloat16_as_ushort(ha) | ((uint32_t)__bfloat16_as_ushort(hb) << 16);
}

/* ================= prep ================= */
__global__ void prep_kernel(const float* __restrict__ qkv_w, const float* __restrict__ proj_w,
                            const float* __restrict__ bias_table, const int* __restrict__ rel_idx)
{
    int i = blockIdx.x * 256 + threadIdx.x;
    if (i < 576 * 192) {
        float w = qkv_w[i];
        __nv_bfloat16 h = __float2bfloat16(w);
        g_wqh[i] = h;
        g_wql[i] = __float2bfloat16(w - __bfloat162float(h));
    }
    if (i < 192 * 192) {
        float w = proj_w[i];
        __nv_bfloat16 h = __float2bfloat16(w);
        g_wph[i] = h;
        g_wpl[i] = __float2bfloat16(w - __bfloat162float(h));
    }
    if (i < HEADS * NTOK * NTOK) {
        int m = i % NTOK, t = i / NTOK;
        int n = t % NTOK, h = t / NTOK;
        g_bias[i] = bias_table[rel_idx[n * NTOK + m] * HEADS + h];
    }
}

/* ================= mma / ldmatrix / cp.async ================= */
__device__ __forceinline__ void mma16816(float* c, const uint32_t* a, const uint32_t* b) {
    asm volatile(
        "mma.sync.aligned.m16n8k16.row.col.f32.bf16.bf16.f32 "
        "{%0,%1,%2,%3}, {%4,%5,%6,%7}, {%8,%9}, {%0,%1,%2,%3};"
        : "+f"(c[0]), "+f"(c[1]), "+f"(c[2]), "+f"(c[3])
        : "r"(a[0]), "r"(a[1]), "r"(a[2]), "r"(a[3]), "r"(b[0]), "r"(b[1]));
}
__device__ __forceinline__ void ldm_x4(uint32_t* r, uint32_t addr) {
    asm volatile("ldmatrix.sync.aligned.m8n8.x4.shared.b16 {%0,%1,%2,%3}, [%4];"
                 : "=r"(r[0]), "=r"(r[1]), "=r"(r[2]), "=r"(r[3]) : "r"(addr));
}
__device__ __forceinline__ void cp16(uint32_t dst, const void* src) {
    asm volatile("cp.async.cg.shared.global [%0], [%1], 16;" :: "r"(dst), "l"(src));
}

/* ================ GEMM v3: 512 thr, 16 warps 4Mx4N, ldmatrix frags ================
   A (128x192 fp32) hi/lo-split once into smem (rows pad 400 B);
   B chunks (192x64 bf16 hi/lo, rows pad 144 B) cp.async double-buffered. */
#define APAD_B 400
#define A_H    0
#define A_L    (128 * APAD_B)                  /* 51200  */
#define B_BASE (2 * 128 * APAD_B)              /* 102400 */
#define B_STEP 55296
#define B_LO   27648
#define GEMM_SMEM (B_BASE + 2 * B_STEP)        /* 212992 */

__global__ __launch_bounds__(512, 1)
void gemm_bf16x3(const float* __restrict__ A,
                 const __nv_bfloat16* __restrict__ Bhi,
                 const __nv_bfloat16* __restrict__ Blo,
                 const float* __restrict__ bias,
                 float* __restrict__ C, int ldc, int NT)
{
    extern __shared__ char smc[];
    uint32_t sb;
    asm("{ .reg .u64 t; cvta.to.shared.u64 t, %1; cvt.u32.u64 %0, t; }" : "=r"(sb) : "l"(smc));

    const int tid = threadIdx.x, wid = tid >> 5, lane = tid & 31;
    const int mtile = blockIdx.x;
    const int wm = (wid & 3) * 32;             /* 4 M groups of 32 */
    const int wn = (wid >> 2) * 48;            /* 4 N groups of 48 */
    const int L  = 3 * NT;

    const int l16 = lane & 15;
    const int hi16 = (lane >> 4) * 16;         /* +16 bytes for k+8 half */

    /* per-lane ldmatrix base offsets (constant across chunks) */
    const uint32_t aoffH0 = A_H + (uint32_t)(wm +      l16) * APAD_B + hi16;
    const uint32_t aoffH1 = A_H + (uint32_t)(wm + 16 + l16) * APAD_B + hi16;
    const uint32_t aoffL0 = aoffH0 + (A_L - A_H);
    const uint32_t aoffL1 = aoffH1 + (A_L - A_H);
    uint32_t boff[3];
    #pragma unroll
    for (int p = 0; p < 3; p++)
        boff[p] = (uint32_t)(wn + p * 16 + l16) * 144 + hi16;

    auto prefetch = [&](int idx) {
        int nt = idx / 3, kc = idx - nt * 3;
        const __nv_bfloat16* bh = Bhi + (size_t)nt * 192 * 192 + kc * 64;
        const __nv_bfloat16* bl = Blo + (size_t)nt * 192 * 192 + kc * 64;
        uint32_t dst = sb + B_BASE + (idx & 1) * B_STEP;
        #pragma unroll
        for (int it = 0; it < 3; it++) {
            int g = tid + it * 512;            /* 1536 groups */
            int row = g >> 3, c8 = g & 7;
            cp16(dst + row * 144 + c8 * 16, bh + row * 192 + c8 * 8);
            cp16(dst + B_LO + row * 144 + c8 * 16, bl + row * 192 + c8 * 8);
        }
        asm volatile("cp.async.commit_group;" ::: "memory");
    };

    prefetch(0);
    if (L > 1) prefetch(1);

    /* ---- A: load 128x192 fp32, split hi/lo into smem (once) ---- */
    {
        const float* Abase = A + (size_t)mtile * 128 * 192;
        #pragma unroll
        for (int it = 0; it < 12; it++) {
            int g = tid + it * 512;            /* 6144 float4 groups */
            int row = g / 48, c4 = (g % 48) * 4;
            float4 f = *(const float4*)(Abase + row * 192 + c4);
            uint32_t h0 = pack_bf2(f.x, f.y), h1 = pack_bf2(f.z, f.w);
            float rx = f.x - __bfloat162float(__ushort_as_bfloat16((unsigned short)h0));
            float ry = f.y - __bfloat162float(__ushort_as_bfloat16((unsigned short)(h0 >> 16)));
            float rz = f.z - __bfloat162float(__ushort_as_bfloat16((unsigned short)h1));
            float rw = f.w - __bfloat162float(__ushort_as_bfloat16((unsigned short)(h1 >> 16)));
            *(uint2*)(smc + A_H + row * APAD_B + c4 * 2) = make_uint2(h0, h1);
            *(uint2*)(smc + A_L + row * APAD_B + c4 * 2) =
                make_uint2(pack_bf2(rx, ry), pack_bf2(rz, rw));
        }
    }
    __syncthreads();

    float acc[2][6][4];

    for (int nt = 0; nt < NT; nt++) {
        #pragma unroll
        for (int mf = 0; mf < 2; mf++)
            #pragma unroll
            for (int nf = 0; nf < 6; nf++)
                #pragma unroll
                for (int j = 0; j < 4; j++) acc[mf][nf][j] = 0.f;

        for (int kc = 0; kc < 3; kc++) {
            const int idx = nt * 3 + kc;
            if (idx < L - 1) asm volatile("cp.async.wait_group 1;" ::: "memory");
            else             asm volatile("cp.async.wait_group 0;" ::: "memory");
            __syncthreads();

            const uint32_t bbH = sb + B_BASE + (idx & 1) * B_STEP;
            const uint32_t bbL = bbH + B_LO;
            const uint32_t akc = sb + kc * 128;   /* A byte offset for this chunk */

            #pragma unroll
            for (int ks = 0; ks < 4; ks++) {
                const uint32_t ka = akc + ks * 32;
                const uint32_t kb = ks * 32;

                uint32_t ah[2][4], al[2][4];
                ldm_x4(ah[0], ka + aoffH0);
                ldm_x4(ah[1], ka + aoffH1);
                ldm_x4(al[0], ka + aoffL0);
                ldm_x4(al[1], ka + aoffL1);

                uint32_t bh[6][2], bl[6][2];
                #pragma unroll
                for (int p = 0; p < 3; p++) {
                    uint32_t t[4];
                    ldm_x4(t, bbH + boff[p] + kb);
                    bh[2*p][0] = t[0]; bh[2*p+1][0] = t[1];
                    bh[2*p][1] = t[2]; bh[2*p+1][1] = t[3];
                    ldm_x4(t, bbL + boff[p] + kb);
                    bl[2*p][0] = t[0]; bl[2*p+1][0] = t[1];
                    bl[2*p][1] = t[2]; bl[2*p+1][1] = t[3];
                }

                #pragma unroll
                for (int mf = 0; mf < 2; mf++)
                    #pragma unroll
                    for (int nf = 0; nf < 6; nf++) {
                        mma16816(acc[mf][nf], ah[mf], bh[nf]);
                        mma16816(acc[mf][nf], ah[mf], bl[nf]);
                        mma16816(acc[mf][nf], al[mf], bh[nf]);
                    }
            }
            __syncthreads();
            if (idx + 2 < L) prefetch(idx + 2);
        }

        /* ---- epilogue for this ntile ---- */
        #pragma unroll
        for (int mf = 0; mf < 2; mf++) {
            size_t r0 = (size_t)mtile * 128 + wm + mf * 16 + (lane >> 2);
            #pragma unroll
            for (int nf = 0; nf < 6; nf++) {
                int c = nt * 192 + wn + nf * 8 + (lane & 3) * 2;
                float b0 = __ldg(bias + c), b1 = __ldg(bias + c + 1);
                *(float2*)(C + r0 * ldc + c) =
                    make_float2(acc[mf][nf][0] + b0, acc[mf][nf][1] + b1);
                *(float2*)(C + (r0 + 8) * ldc + c) =
                    make_float2(acc[mf][nf][2] + b0, acc[mf][nf][3] + b1);
            }
        }
    }
}

/* ================= K2: tensorized per-window attention (unchanged, passing) ========== */
__global__ __launch_bounds__(128, 3)
void attn_win()
{
    __shared__ __nv_bfloat16 sQh[64 * 36], sQl[64 * 36];
    __shared__ __nv_bfloat16 sKh[56 * 36], sKl[56 * 36];
    __shared__ __nv_bfloat16 sVh[32 * 66], sVl[32 * 66];

    const int tid  = threadIdx.x;
    const int wid  = tid >> 5, lane = tid & 31;
    const int b    = blockIdx.x;
    const int l4   = lane >> 2, lm = lane & 3;

    for (int i = tid; i < 64 * 36; i += 128) { sQh[i] = __nv_bfloat16(0.f); sQl[i] = __nv_bfloat16(0.f); }
    for (int i = tid; i < 56 * 36; i += 128) { sKh[i] = __nv_bfloat16(0.f); sKl[i] = __nv_bfloat16(0.f); }
    for (int i = tid; i < 32 * 66; i += 128) { sVh[i] = __nv_bfloat16(0.f); sVl[i] = __nv_bfloat16(0.f); }

    const float* qkvw = g_qkv + (size_t)b * (NTOK * 576);
    const int r0 = wid * 16 + l4;

    for (int h = 0; h < HEADS; h++) {
        __syncthreads();
        for (int idx = tid; idx < NTOK * 32; idx += 128) {
            int r = idx >> 5, c = idx & 31;
            const float* rowp = qkvw + r * 576 + h * 32 + c;
            float qv = rowp[0] * QSCALE;
            float kv = rowp[192];
            float vv = rowp[384];
            __nv_bfloat16 qh = __float2bfloat16(qv);
            __nv_bfloat16 kh = __float2bfloat16(kv);
            __nv_bfloat16 vh = __float2bfloat16(vv);
            sQh[r * 36 + c] = qh; sQl[r * 36 + c] = __float2bfloat16(qv - __bfloat162float(qh));
            sKh[r * 36 + c] = kh; sKl[r * 36 + c] = __float2bfloat16(kv - __bfloat162float(kh));
            sVh[c * 66 + r] = vh; sVl[c * 66 + r] = __float2bfloat16(vv - __bfloat162float(vh));
        }
        __syncthreads();

        uint32_t qh[2][4], ql[2][4];
        #pragma unroll
        for (int kf = 0; kf < 2; kf++)
            #pragma unroll
            for (int j = 0; j < 4; j++) {
                int rr = r0 + (j & 1) * 8;
                int kx = kf * 16 + lm * 2 + (j >> 1) * 8;
                qh[kf][j] = *(const uint32_t*)&sQh[rr * 36 + kx];
                ql[kf][j] = *(const uint32_t*)&sQl[rr * 36 + kx];
            }

        float acc[7][4];
        #pragma unroll
        for (int nf = 0; nf < 7; nf++)
            #pragma unroll
            for (int j = 0; j < 4; j++) acc[nf][j] = 0.f;

        #pragma unroll
        for (int nf = 0; nf < 7; nf++) {
            int n = nf * 8 + l4;
            #pragma unroll
            for (int kf = 0; kf < 2; kf++) {
                uint32_t bh[2], bl[2];
                bh[0] = *(const uint32_t*)&sKh[n * 36 + kf * 16 + lm * 2];
                bh[1] = *(const uint32_t*)&sKh[n * 36 + kf * 16 + lm * 2 + 8];
                bl[0] = *(const uint32_t*)&sKl[n * 36 + kf * 16 + lm * 2];
                bl[1] = *(const uint32_t*)&sKl[n * 36 + kf * 16 + lm * 2 + 8];
                mma16816(acc[nf], qh[kf], bh);
                mma16816(acc[nf], ql[kf], bh);
                mma16816(acc[nf], qh[kf], bl);
            }
        }

        const int ra = r0, rb = r0 + 8;
        const float* biasA = g_bias + (h * NTOK + ra) * NTOK;
        const float* biasB = g_bias + (h * NTOK + rb) * NTOK;
        float ma = -1e30f, mb = -1e30f;
        #pragma unroll
        for (int nf = 0; nf < 7; nf++) {
            int c0 = nf * 8 + lm * 2, c1 = c0 + 1;
            float ba0 = (ra < NTOK && c0 < NTOK) ? __ldg(biasA + c0) : 0.f;
            float ba1 = (ra < NTOK && c1 < NTOK) ? __ldg(biasA + c1) : 0.f;
            float bb0 = (rb < NTOK && c0 < NTOK) ? __ldg(biasB + c0) : 0.f;
            float bb1 = (rb < NTOK && c1 < NTOK) ? __ldg(biasB + c1) : 0.f;
            acc[nf][0] = (c0 < NTOK) ? acc[nf][0] + ba0 : -1e30f;
            acc[nf][1] = (c1 < NTOK) ? acc[nf][1] + ba1 : -1e30f;
            acc[nf][2] = (c0 < NTOK) ? acc[nf][2] + bb0 : -1e30f;
            acc[nf][3] = (c1 < NTOK) ? acc[nf][3] + bb1 : -1e30f;
            ma = fmaxf(ma, fmaxf(acc[nf][0], acc[nf][1]));
            mb = fmaxf(mb, fmaxf(acc[nf][2], acc[nf][3]));
        }
        ma = fmaxf(ma, __shfl_xor_sync(0xffffffffu, ma, 1));
        ma = fmaxf(ma, __shfl_xor_sync(0xffffffffu, ma, 2));
        mb = fmaxf(mb, __shfl_xor_sync(0xffffffffu, mb, 1));
        mb = fmaxf(mb, __shfl_xor_sync(0xffffffffu, mb, 2));

        float sa = 0.f, sb2 = 0.f;
        #pragma unroll
        for (int nf = 0; nf < 7; nf++) {
            acc[nf][0] = __expf(acc[nf][0] - ma);
            acc[nf][1] = __expf(acc[nf][1] - ma);
            acc[nf][2] = __expf(acc[nf][2] - mb);
            acc[nf][3] = __expf(acc[nf][3] - mb);
            sa  += acc[nf][0] + acc[nf][1];
            sb2 += acc[nf][2] + acc[nf][3];
        }
        sa  += __shfl_xor_sync(0xffffffffu, sa, 1);
        sa  += __shfl_xor_sync(0xffffffffu, sa, 2);
        sb2 += __shfl_xor_sync(0xffffffffu, sb2, 1);
        sb2 += __shfl_xor_sync(0xffffffffu, sb2, 2);
        float inva = 1.f / sa, invb = 1.f / sb2;
        #pragma unroll
        for (int nf = 0; nf < 7; nf++) {
            acc[nf][0] *= inva; acc[nf][1] *= inva;
            acc[nf][2] *= invb; acc[nf][3] *= invb;
        }

        uint32_t pah[4][4], pal[4][4];
        #pragma unroll
        for (int kf = 0; kf < 4; kf++) {
            #pragma unroll
            for (int half = 0; half < 2; half++) {
                int nf = 2 * kf + half;
                if (nf < 7) {
                    float p0 = acc[nf][0], p1 = acc[nf][1];
                    float p2 = acc[nf][2], p3 = acc[nf][3];
                    uint32_t h01 = pack_bf2(p0, p1), h23 = pack_bf2(p2, p3);
                    float r0f = p0 - __bfloat162float(__ushort_as_bfloat16((unsigned short)h01));
                    float r1f = p1 - __bfloat162float(__ushort_as_bfloat16((unsigned short)(h01 >> 16)));
                    float r2f = p2 - __bfloat162float(__ushort_as_bfloat16((unsigned short)h23));
                    float r3f = p3 - __bfloat162float(__ushort_as_bfloat16((unsigned short)(h23 >> 16)));
                    pah[kf][half * 2]     = h01;
                    pah[kf][half * 2 + 1] = h23;
                    pal[kf][half * 2]     = pack_bf2(r0f, r1f);
                    pal[kf][half * 2 + 1] = pack_bf2(r2f, r3f);
                } else {
                    pah[kf][half * 2] = 0u; pah[kf][half * 2 + 1] = 0u;
                    pal[kf][half * 2] = 0u; pal[kf][half * 2 + 1] = 0u;
                }
            }
        }

        float oacc[4][4];
        #pragma unroll
        for (int nf = 0; nf < 4; nf++)
            #pragma unroll
            for (int j = 0; j < 4; j++) oacc[nf][j] = 0.f;

        #pragma unroll
        for (int nf = 0; nf < 4; nf++) {
            int dh = nf * 8 + l4;
            #pragma unroll
            for (int kf = 0; kf < 4; kf++) {
                uint32_t bh[2], bl[2];
                bh[0] = *(const uint32_t*)&sVh[dh * 66 + kf * 16 + lm * 2];
                bh[1] = *(const uint32_t*)&sVh[dh * 66 + kf * 16 + lm * 2 + 8];
                bl[0] = *(const uint32_t*)&sVl[dh * 66 + kf * 16 + lm * 2];
                bl[1] = *(const uint32_t*)&sVl[dh * 66 + kf * 16 + lm * 2 + 8];
                mma16816(oacc[nf], pah[kf], bh);
                mma16816(oacc[nf], pal[kf], bh);
                mma16816(oacc[nf], pah[kf], bl);
            }
        }

        if (ra < NTOK) {
            float* orow = g_attn + ((size_t)b * NTOK + ra) * DIM + h * DH;
            #pragma unroll
            for (int nf = 0; nf < 4; nf++)
                *(float2*)(orow + nf * 8 + lm * 2) = make_float2(oacc[nf][0], oacc[nf][1]);
        }
        if (rb < NTOK) {
            float* orow = g_attn + ((size_t)b * NTOK + rb) * DIM + h * DH;
            #pragma unroll
            for (int nf = 0; nf < 4; nf++)
                *(float2*)(orow + nf * 8 + lm * 2) = make_float2(oacc[nf][2], oacc[nf][3]);
        }
    }
}

/* ================= host ================= */
extern "C" void kernel_launch(void* const* d_in, const int* in_sizes, int n_in,
                              void* d_out, int out_size)
{
    const float* x          = (const float*)d_in[0];
    const float* qkv_w      = (const float*)d_in[1];
    const float* qkv_b      = (const float*)d_in[2];
    const float* proj_w     = (const float*)d_in[3];
    const float* proj_b     = (const float*)d_in[4];
    const float* bias_table = (const float*)d_in[5];
    const int*   rel_idx    = (const int*)d_in[6];
    float*       out        = (float*)d_out;

    const int nB = in_sizes[0] / (NTOK * DIM);       /* 4096 */
    const int mt = (nB * NTOK) / 128;                /* 1568 */

    void *p_qkv, *p_attn, *p_wqh, *p_wql, *p_wph, *p_wpl;
    cudaGetSymbolAddress(&p_qkv,  g_qkv);
    cudaGetSymbolAddress(&p_attn, g_attn);
    cudaGetSymbolAddress(&p_wqh,  g_wqh);
    cudaGetSymbolAddress(&p_wql,  g_wql);
    cudaGetSymbolAddress(&p_wph,  g_wph);
    cudaGetSymbolAddress(&p_wpl,  g_wpl);

    cudaFuncSetAttribute(gemm_bf16x3, cudaFuncAttributeMaxDynamicSharedMemorySize, GEMM_SMEM);

    prep_kernel<<<432, 256>>>(qkv_w, proj_w, bias_table, rel_idx);

    gemm_bf16x3<<<mt, 512, GEMM_SMEM>>>(
        x, (const __nv_bfloat16*)p_wqh, (const __nv_bfloat16*)p_wql,
        qkv_b, (float*)p_qkv, 576, 3);

    attn_win<<<nB, 128>>>();

    gemm_bf16x3<<<mt, 512, GEMM_SMEM>>>(
        (const float*)p_attn, (const __nv_bfloat16*)p_wph, (const __nv_bfloat16*)p_wpl,
        proj_b, out, 192, 1);
}